// round 2
// baseline (speedup 1.0000x reference)
#include <cuda_runtime.h>
#include <math.h>

// ---------------------------------------------------------------------------
// HardConstrainedMLP:
//   y = MLP(concat(b,c));  q = b @ Aaug_inv^T;  P = I - Aaug^T Aaug_inv^T
//   s_{k+1} = s_k + w*(tk - zk),  zk = s_k P + q,
//   tk = [toproj[:250], SOC(toproj[250:])],  toproj = (2zk - s - 2*sig*y)/(1+2*sig)
//   out = s_K P + q
// Rows (batch samples) are fully independent -> persistent per-CTA solve,
// no inter-CTA synchronization, 1000 iterations inside one kernel.
// ---------------------------------------------------------------------------

#define D_DIM   500
#define NHALF   250
#define BATCHSZ 1024
#define HDIM    512
#define NIT     1000
#define ROWS    8
#define NBLK    (BATCHSZ / ROWS)   // 128

#define OMEGA_F 1.8f
#define SIGMA_F 0.1f
#define INV12   (1.0f / 1.2f)

// scratch (device globals: no allocations allowed)
__device__ float g_P[D_DIM * D_DIM];
__device__ float g_AinvT[NHALF * D_DIM];
__device__ float g_y[BATCHSZ * D_DIM];
__device__ float g_q[BATCHSZ * D_DIM];

// Packed fp32x2 FMA (Blackwell FFMA2; only reachable via PTX).
__device__ __forceinline__ float2 ffma2(float2 a, float2 b, float2 c) {
    float2 d;
    asm("{\n\t"
        ".reg .b64 ra, rb, rc, rd;\n\t"
        "mov.b64 ra, {%2,%3};\n\t"
        "mov.b64 rb, {%4,%5};\n\t"
        "mov.b64 rc, {%6,%7};\n\t"
        "fma.rn.f32x2 rd, ra, rb, rc;\n\t"
        "mov.b64 {%0,%1}, rd;\n\t"
        "}"
        : "=f"(d.x), "=f"(d.y)
        : "f"(a.x), "f"(a.y), "f"(b.x), "f"(b.y), "f"(c.x), "f"(c.y));
    return d;
}

// ---------------------------------------------------------------------------
// 1) Transpose Aaug_inv [500,250] -> AinvT [250,500] (coalesced consumers)
// ---------------------------------------------------------------------------
__global__ void transpose_ainv_kernel(const float* __restrict__ Ainv) {
    int j = blockIdx.x;  // 0..499
    for (int m = threadIdx.x; m < NHALF; m += blockDim.x)
        g_AinvT[m * D_DIM + j] = Ainv[j * NHALF + m];
}

// ---------------------------------------------------------------------------
// 2) P[k][j] = (k==j) - sum_m Aaug[m][k] * Ainv[j][m]
// ---------------------------------------------------------------------------
__global__ void compute_P_kernel(const float* __restrict__ Aaug) {
    __shared__ float acol[NHALF];
    int k = blockIdx.x;  // 0..499
    for (int m = threadIdx.x; m < NHALF; m += blockDim.x)
        acol[m] = Aaug[m * D_DIM + k];
    __syncthreads();
    int j = threadIdx.x;
    if (j < D_DIM) {
        float acc = (j == k) ? 1.0f : 0.0f;
        for (int m = 0; m < NHALF; ++m)
            acc -= acol[m] * g_AinvT[m * D_DIM + j];
        g_P[k * D_DIM + j] = acc;
    }
}

// ---------------------------------------------------------------------------
// 3) MLP front-end: 8 rows per block, 512 threads. Produces g_y, g_q.
// ---------------------------------------------------------------------------
__global__ __launch_bounds__(512) void mlp_kernel(
    const float* __restrict__ bin, const float* __restrict__ cin,
    const float* __restrict__ W1, const float* __restrict__ b1,
    const float* __restrict__ W2, const float* __restrict__ b2,
    const float* __restrict__ W3, const float* __restrict__ b3) {
    __shared__ __align__(16) float xT[D_DIM * ROWS];   // 16000 B, [k][r]
    __shared__ __align__(16) float h1T[HDIM * ROWS];   // 16384 B
    __shared__ __align__(16) float h2T[HDIM * ROWS];   // 16384 B
    int tid = threadIdx.x;
    int rb = blockIdx.x * ROWS;

    for (int i = tid; i < D_DIM * ROWS; i += 512) {
        int k = i >> 3, r = i & 7;
        xT[i] = (k < NHALF) ? bin[(rb + r) * NHALF + k]
                            : cin[(rb + r) * NHALF + (k - NHALF)];
    }
    __syncthreads();

    // layer 1: h1 = relu(x @ W1 + b1)
    {
        float acc[ROWS];
        float bias = b1[tid];
#pragma unroll
        for (int r = 0; r < ROWS; ++r) acc[r] = bias;
        for (int k = 0; k < D_DIM; ++k) {
            float w = W1[k * HDIM + tid];
            float4 xa = *(const float4*)&xT[k * ROWS];
            float4 xb = *(const float4*)&xT[k * ROWS + 4];
            acc[0] += xa.x * w; acc[1] += xa.y * w; acc[2] += xa.z * w; acc[3] += xa.w * w;
            acc[4] += xb.x * w; acc[5] += xb.y * w; acc[6] += xb.z * w; acc[7] += xb.w * w;
        }
#pragma unroll
        for (int r = 0; r < ROWS; ++r) h1T[tid * ROWS + r] = fmaxf(acc[r], 0.0f);
    }
    __syncthreads();

    // layer 2: h2 = relu(h1 @ W2 + b2)
    {
        float acc[ROWS];
        float bias = b2[tid];
#pragma unroll
        for (int r = 0; r < ROWS; ++r) acc[r] = bias;
        for (int k = 0; k < HDIM; ++k) {
            float w = W2[k * HDIM + tid];
            float4 xa = *(const float4*)&h1T[k * ROWS];
            float4 xb = *(const float4*)&h1T[k * ROWS + 4];
            acc[0] += xa.x * w; acc[1] += xa.y * w; acc[2] += xa.z * w; acc[3] += xa.w * w;
            acc[4] += xb.x * w; acc[5] += xb.y * w; acc[6] += xb.z * w; acc[7] += xb.w * w;
        }
#pragma unroll
        for (int r = 0; r < ROWS; ++r) h2T[tid * ROWS + r] = fmaxf(acc[r], 0.0f);
    }
    __syncthreads();

    // layer 3 (y = h2 @ W3 + b3) and q = bv @ Ainv^T
    if (tid < D_DIM) {
        float acc[ROWS];
        float bias = b3[tid];
#pragma unroll
        for (int r = 0; r < ROWS; ++r) acc[r] = bias;
        for (int k = 0; k < HDIM; ++k) {
            float w = W3[k * D_DIM + tid];
            float4 xa = *(const float4*)&h2T[k * ROWS];
            float4 xb = *(const float4*)&h2T[k * ROWS + 4];
            acc[0] += xa.x * w; acc[1] += xa.y * w; acc[2] += xa.z * w; acc[3] += xa.w * w;
            acc[4] += xb.x * w; acc[5] += xb.y * w; acc[6] += xb.z * w; acc[7] += xb.w * w;
        }
#pragma unroll
        for (int r = 0; r < ROWS; ++r) g_y[(rb + r) * D_DIM + tid] = acc[r];

        float qa[ROWS];
#pragma unroll
        for (int r = 0; r < ROWS; ++r) qa[r] = 0.0f;
        for (int m = 0; m < NHALF; ++m) {
            float w = g_AinvT[m * D_DIM + tid];
            float4 xa = *(const float4*)&xT[m * ROWS];
            float4 xb = *(const float4*)&xT[m * ROWS + 4];
            qa[0] += xa.x * w; qa[1] += xa.y * w; qa[2] += xa.z * w; qa[3] += xa.w * w;
            qa[4] += xb.x * w; qa[5] += xb.y * w; qa[6] += xb.z * w; qa[7] += xb.w * w;
        }
#pragma unroll
        for (int r = 0; r < ROWS; ++r) g_q[(rb + r) * D_DIM + tid] = qa[r];
    }
}

// ---------------------------------------------------------------------------
// 4) Persistent solver: 128 blocks x 256 threads, 8 rows/block, 1000 iters.
//    thread t owns columns (2t, 2t+1) for all 8 rows.
// ---------------------------------------------------------------------------
__device__ __forceinline__ void matvec8(const float2* __restrict__ Pp,
                                        const float* sT,
                                        const float2* qv, float2* z) {
#pragma unroll
    for (int r = 0; r < ROWS; ++r) z[r] = qv[r];
#pragma unroll 4
    for (int k = 0; k < D_DIM; ++k) {
        float2 p = __ldg(&Pp[k * NHALF]);
        float4 sa = *(const float4*)&sT[k * ROWS];
        float4 sb = *(const float4*)&sT[k * ROWS + 4];
        z[0] = ffma2(p, make_float2(sa.x, sa.x), z[0]);
        z[1] = ffma2(p, make_float2(sa.y, sa.y), z[1]);
        z[2] = ffma2(p, make_float2(sa.z, sa.z), z[2]);
        z[3] = ffma2(p, make_float2(sa.w, sa.w), z[3]);
        z[4] = ffma2(p, make_float2(sb.x, sb.x), z[4]);
        z[5] = ffma2(p, make_float2(sb.y, sb.y), z[5]);
        z[6] = ffma2(p, make_float2(sb.z, sb.z), z[6]);
        z[7] = ffma2(p, make_float2(sb.w, sb.w), z[7]);
    }
}

__device__ __forceinline__ float soc_proj(float v, int col, float nu, float tv) {
    if (col < NHALF) return v;            // passthrough half
    if (nu <= tv)  return v;              // inside cone
    if (nu <= -tv) return 0.0f;           // polar cone
    float hs = 0.5f * (tv + nu);
    if (col == D_DIM - 1) return hs;      // t component
    return hs * v / (nu + 1e-12f);        // u components
}

__global__ __launch_bounds__(256) void solver_kernel(float* __restrict__ out) {
    __shared__ __align__(16) float sT[D_DIM * ROWS];   // [k][r], 16000 B
    __shared__ float part[ROWS * 256];                 // 8192 B
    __shared__ float normu[ROWS];
    __shared__ float tval[ROWS];

    int tid = threadIdx.x;
    int rb = blockIdx.x * ROWS;
    bool act = tid < NHALF;
    int c0 = 2 * tid;

    for (int i = tid; i < D_DIM * ROWS; i += 256) sT[i] = 0.0f;

    float2 qv[ROWS], yv[ROWS], sv[ROWS], z[ROWS], tp[ROWS];
    if (act) {
#pragma unroll
        for (int r = 0; r < ROWS; ++r) {
            qv[r] = *(const float2*)&g_q[(rb + r) * D_DIM + c0];
            yv[r] = *(const float2*)&g_y[(rb + r) * D_DIM + c0];
            sv[r] = make_float2(0.0f, 0.0f);
        }
    }
    __syncthreads();

    const float2* Pp = ((const float2*)g_P) + tid;

    for (int it = 0; it < NIT; ++it) {
        if (act) {
            matvec8(Pp, sT, qv, z);
#pragma unroll
            for (int r = 0; r < ROWS; ++r) {
                tp[r].x = (2.0f * z[r].x - sv[r].x - 2.0f * SIGMA_F * yv[r].x) * INV12;
                tp[r].y = (2.0f * z[r].y - sv[r].y - 2.0f * SIGMA_F * yv[r].y) * INV12;
                float cx = (c0 >= NHALF && c0 <= D_DIM - 2) ? tp[r].x * tp[r].x : 0.0f;
                float cy = (c0 + 1 >= NHALF && c0 + 1 <= D_DIM - 2) ? tp[r].y * tp[r].y : 0.0f;
                part[r * 256 + tid] = cx + cy;
            }
            if (tid == NHALF - 1) {
#pragma unroll
                for (int r = 0; r < ROWS; ++r) tval[r] = tp[r].y;  // col 499
            }
        } else {
#pragma unroll
            for (int r = 0; r < ROWS; ++r) part[r * 256 + tid] = 0.0f;
        }
        __syncthreads();

        {   // warp w reduces row w (deterministic)
            int w = tid >> 5, l = tid & 31;
            float s = 0.0f;
#pragma unroll
            for (int j = 0; j < 8; ++j) s += part[w * 256 + j * 32 + l];
#pragma unroll
            for (int off = 16; off > 0; off >>= 1)
                s += __shfl_xor_sync(0xffffffffu, s, off);
            if (l == 0) normu[w] = sqrtf(s);
        }
        __syncthreads();

        int changed = 0;
        if (act) {
#pragma unroll
            for (int r = 0; r < ROWS; ++r) {
                float nu = normu[r], tv = tval[r];
                float2 tk;
                tk.x = soc_proj(tp[r].x, c0, nu, tv);
                tk.y = soc_proj(tp[r].y, c0 + 1, nu, tv);
                float2 sn;
                sn.x = sv[r].x + OMEGA_F * (tk.x - z[r].x);
                sn.y = sv[r].y + OMEGA_F * (tk.y - z[r].y);
                changed |= (sn.x != sv[r].x) | (sn.y != sv[r].y);
                sv[r] = sn;
                sT[c0 * ROWS + r] = sn.x;
                sT[(c0 + 1) * ROWS + r] = sn.y;
            }
        }
        // bitwise fixed point => every later iteration identical => safe exit
        if (!__syncthreads_or(changed)) break;
    }

    // final projection zk1 = s P + q
    if (act) {
        matvec8(Pp, sT, qv, z);
#pragma unroll
        for (int r = 0; r < ROWS; ++r)
            *(float2*)&out[(rb + r) * D_DIM + c0] = z[r];
    }
}

// ---------------------------------------------------------------------------
extern "C" void kernel_launch(void* const* d_in, const int* in_sizes, int n_in,
                              void* d_out, int out_size) {
    const float* b    = (const float*)d_in[0];
    const float* c    = (const float*)d_in[1];
    const float* W1   = (const float*)d_in[2];
    const float* b1   = (const float*)d_in[3];
    const float* W2   = (const float*)d_in[4];
    const float* b2   = (const float*)d_in[5];
    const float* W3   = (const float*)d_in[6];
    const float* b3   = (const float*)d_in[7];
    const float* Aaug = (const float*)d_in[8];
    const float* Ainv = (const float*)d_in[9];
    float* out = (float*)d_out;

    transpose_ainv_kernel<<<D_DIM, 256>>>(Ainv);
    compute_P_kernel<<<D_DIM, 512>>>(Aaug);
    mlp_kernel<<<NBLK, 512>>>(b, c, W1, b1, W2, b2, W3, b3);
    solver_kernel<<<NBLK, 256>>>(out);
}